// round 6
// baseline (speedup 1.0000x reference)
#include <cuda_runtime.h>

// Sum-reduce 20M fp32 values (full sparse sum == values.sum(); indices unused).
// HBM-bound streaming read of 80 MB. Single fused kernel:
//   - grid-stride float4 loads, 4-way unrolled with independent accumulators
//     (MLP=4 per thread) at coalesced offsets
//   - __ldcs streaming hint (read-once data, don't retain in L2)
//   - block partials accumulated into __device__ scratch via atomicAdd;
//     last block (atomic counter) writes d_out and resets scratch for the
//     next graph replay (deterministic, allocation-free).

__device__ float         g_partial = 0.0f;
__device__ unsigned int  g_count   = 0;

__global__ void __launch_bounds__(256) sum_kernel(const float* __restrict__ vals,
                                                  long long n, float* __restrict__ out,
                                                  int nblocks) {
    long long n4 = n >> 2;
    const float4* v4 = reinterpret_cast<const float4*>(vals);

    long long idx    = blockIdx.x * (long long)blockDim.x + threadIdx.x;
    long long stride = (long long)gridDim.x * blockDim.x;

    float a0 = 0.0f, a1 = 0.0f, a2 = 0.0f, a3 = 0.0f;

    long long i = idx;
    for (; i + 3 * stride < n4; i += 4 * stride) {
        float4 v0 = __ldcs(v4 + i);
        float4 v1 = __ldcs(v4 + i + stride);
        float4 v2 = __ldcs(v4 + i + 2 * stride);
        float4 v3 = __ldcs(v4 + i + 3 * stride);
        a0 += (v0.x + v0.y) + (v0.z + v0.w);
        a1 += (v1.x + v1.y) + (v1.z + v1.w);
        a2 += (v2.x + v2.y) + (v2.z + v2.w);
        a3 += (v3.x + v3.y) + (v3.z + v3.w);
    }
    for (; i < n4; i += stride) {
        float4 v = __ldcs(v4 + i);
        a0 += (v.x + v.y) + (v.z + v.w);
    }
    // scalar tail (n not divisible by 4)
    for (long long j = (n4 << 2) + idx; j < n; j += stride) {
        a0 += __ldcs(vals + j);
    }

    float acc = (a0 + a1) + (a2 + a3);

    // warp reduce
    #pragma unroll
    for (int off = 16; off > 0; off >>= 1)
        acc += __shfl_down_sync(0xFFFFFFFFu, acc, off);

    __shared__ float warp_sums[8];  // 256 threads = 8 warps
    int lane = threadIdx.x & 31;
    int wid  = threadIdx.x >> 5;
    if (lane == 0) warp_sums[wid] = acc;
    __syncthreads();

    if (wid == 0) {
        float s = (lane < 8) ? warp_sums[lane] : 0.0f;
        #pragma unroll
        for (int off = 4; off > 0; off >>= 1)
            s += __shfl_down_sync(0xFFFFFFFFu, s, off);

        if (lane == 0) {
            atomicAdd(&g_partial, s);
            __threadfence();
            unsigned int done = atomicAdd(&g_count, 1u);
            if (done == (unsigned int)nblocks - 1u) {
                // last block: publish result and reset scratch for next replay
                out[0]    = g_partial;
                g_partial = 0.0f;
                g_count   = 0u;
            }
        }
    }
}

extern "C" void kernel_launch(void* const* d_in, const int* in_sizes, int n_in,
                              void* d_out, int out_size) {
    const float* vals = (const float*)d_in[0];
    long long n = (long long)in_sizes[0];
    float* out = (float*)d_out;

    int grid = 148 * 8;  // 1184 blocks, ~92% occupancy, deep L1tex queues
    sum_kernel<<<grid, 256>>>(vals, n, out, grid);
}

// round 8
// speedup vs baseline: 1.3200x; 1.3200x over previous
#include <cuda_runtime.h>

// Sum-reduce 20M fp32 values (full sparse sum == values.sum(); indices unused).
// HBM-bound streaming read of 80 MB.
// R6/R7: exact R0 load loop (plain float4 grid-stride — ptxas front-batches the
// LDGs itself; __ldcs and manual stride-unroll both REGRESSED throughput),
// fused into a single kernel via last-block-counter finalize so the graph has
// one node instead of two. R7 = R6 resubmitted after infra failure.

__device__ float         g_partial = 0.0f;
__device__ unsigned int  g_count   = 0;

__global__ void __launch_bounds__(256) sum_kernel(const float* __restrict__ vals,
                                                  long long n, float* __restrict__ out,
                                                  int nblocks) {
    long long n4 = n >> 2;  // number of float4s
    const float4* v4 = reinterpret_cast<const float4*>(vals);

    float acc = 0.0f;
    long long idx = blockIdx.x * (long long)blockDim.x + threadIdx.x;
    long long stride = (long long)gridDim.x * blockDim.x;

    for (long long i = idx; i < n4; i += stride) {
        float4 v = v4[i];
        acc += (v.x + v.y) + (v.z + v.w);
    }
    // tail (n not divisible by 4)
    for (long long i = (n4 << 2) + idx; i < n; i += stride) {
        acc += vals[i];
    }

    // warp reduce
    #pragma unroll
    for (int off = 16; off > 0; off >>= 1)
        acc += __shfl_down_sync(0xFFFFFFFFu, acc, off);

    __shared__ float warp_sums[8];  // 256 threads = 8 warps
    int lane = threadIdx.x & 31;
    int wid  = threadIdx.x >> 5;
    if (lane == 0) warp_sums[wid] = acc;
    __syncthreads();

    if (wid == 0) {
        float s = (lane < 8) ? warp_sums[lane] : 0.0f;
        #pragma unroll
        for (int off = 4; off > 0; off >>= 1)
            s += __shfl_down_sync(0xFFFFFFFFu, s, off);

        if (lane == 0) {
            atomicAdd(&g_partial, s);
            __threadfence();
            unsigned int done = atomicAdd(&g_count, 1u);
            if (done == (unsigned int)nblocks - 1u) {
                // last block: publish result and reset scratch for next replay
                out[0]    = g_partial;
                g_partial = 0.0f;
                g_count   = 0u;
            }
        }
    }
}

extern "C" void kernel_launch(void* const* d_in, const int* in_sizes, int n_in,
                              void* d_out, int out_size) {
    const float* vals = (const float*)d_in[0];
    long long n = (long long)in_sizes[0];
    float* out = (float*)d_out;

    int grid = 148 * 8;  // 1184 blocks = exactly one full-occupancy wave
    sum_kernel<<<grid, 256>>>(vals, n, out, grid);
}